// round 6
// baseline (speedup 1.0000x reference)
#include <cuda_runtime.h>

// ---------------------------------------------------------------------------
// ConvLSTM: B=16, T=16, C=1, H=W=64, HID=64, two layers of 3x3 ConvLSTM cells,
// then a 1x1 conv head with ReLU.
//
// Round 2: packed fma.rn.f32x2 inner loop (2 FP32 FMAs / instruction on
// sm_103a), weights staged in SMEM pre-duplicated as (w,w) 64-bit pairs so a
// single broadcast LDS.64 gives a packed multiplier, 4-input-channel staging
// chunks to amortize barriers, float2 state I/O.
// ---------------------------------------------------------------------------

#define HSZ (16 * 64 * 64 * 64)   // one state buffer: [B=16, HID=64, 64, 64]

__device__ float g_h0[2][HSZ];
__device__ float g_c0[HSZ];
__device__ float g_h1[2][HSZ];
__device__ float g_c1[HSZ];

__device__ __forceinline__ float fsig(float x) {
    return 1.0f / (1.0f + __expf(-x));
}
__device__ __forceinline__ float ftanh(float x) {
    return 2.0f / (1.0f + __expf(-2.0f * x)) - 1.0f;
}

__device__ __forceinline__ unsigned long long packf2(float a, float b) {
    unsigned long long r;
    asm("mov.b64 %0, {%1, %2};" : "=l"(r)
        : "r"(__float_as_uint(a)), "r"(__float_as_uint(b)));
    return r;
}
__device__ __forceinline__ void unpackf2(unsigned long long p, float& a, float& b) {
    unsigned int lo, hi;
    asm("mov.b64 {%0, %1}, %2;" : "=r"(lo), "=r"(hi) : "l"(p));
    a = __uint_as_float(lo);
    b = __uint_as_float(hi);
}
#define FMA2(d, a, b) \
    asm("fma.rn.f32x2 %0, %1, %2, %0;" : "+l"(d) : "l"(a), "l"(b))

__global__ void zero_state_kernel() {
    int i = blockIdx.x * blockDim.x + threadIdx.x;
    if (i < HSZ) {
        g_h0[0][i] = 0.f;
        g_c0[i]    = 0.f;
        g_h1[0][i] = 0.f;
        g_c1[i]    = 0.f;
    }
}

// One ConvLSTM cell step.
//  A    : first CHA input channels (x_t for layer0, h0_new for layer1).
//  Hin  : previous hidden state [B,64,64,64].
//  W    : [256, CHA+64, 3, 3] gate weights, bias: [256].
//  C    : cell state (in-place). Hout: new hidden (ping-pong).
// Grid: (4 spatial 32x32 tiles, 16 hid-blocks of 4 channels, 16 batch).
// Block: 256 threads, each owns a 2x2 pixel micro-tile; the 2 horizontal
// pixels are packed into one f32x2 lane pair.
template <int CHA>
__global__ void __launch_bounds__(256, 2)
convlstm_step(const float* __restrict__ A, int aBatchStride,
              const float* __restrict__ Hin,
              const float* __restrict__ W,
              const float* __restrict__ bias,
              float* __restrict__ C,
              float* __restrict__ Hout)
{
    constexpr int CIN = CHA + 64;
    __shared__ float s_in[4][34 * 34];                 // 4 input-channel halo tiles
    __shared__ unsigned long long s_w2[4][144];        // (w,w) dup pairs: 16 gc x 9 taps

    const int tid = threadIdx.x;
    const int b   = blockIdx.z;
    const int hb  = blockIdx.y;                 // hid base = hb*4
    const int tY0 = (blockIdx.x >> 1) * 32;
    const int tX0 = (blockIdx.x & 1) * 32;
    const int ty2 = (tid >> 4) * 2;             // pixel row base in tile
    const int tx2 = (tid & 15) * 2;             // pixel col base (even)

    unsigned long long acc2[32];                // [gc=16][pr=2], packed over pc
#pragma unroll
    for (int i = 0; i < 32; i++) acc2[i] = 0ULL;

    const float* Abase = A + (size_t)b * aBatchStride;
    const float* Hbase = Hin + ((size_t)b * 64) * 4096;

    for (int ic0 = 0; ic0 < CIN; ic0 += 4) {
        const int nic = (CIN - ic0 < 4) ? (CIN - ic0) : 4;
        __syncthreads();
        // ---- stage nic input halo tiles (zero-padded SAME boundary) ----
        for (int ici = 0; ici < nic; ici++) {
            const int ic = ic0 + ici;
            const float* plane = (ic < CHA) ? (Abase + ic * 4096)
                                            : (Hbase + (ic - CHA) * 4096);
            for (int i = tid; i < 34 * 34; i += 256) {
                int r  = i / 34, cc = i - r * 34;
                int gy = tY0 + r - 1, gx = tX0 + cc - 1;
                float v = 0.f;
                if ((unsigned)gy < 64u && (unsigned)gx < 64u) v = plane[gy * 64 + gx];
                s_in[ici][i] = v;
            }
        }
        // ---- stage duplicated weight pairs for this block's 16 gate chans ----
        for (int i = tid; i < nic * 144; i += 256) {
            int ici = i / 144, rem = i - ici * 144;
            int gc = rem / 9, k = rem - gc * 9;
            int oc = (gc >> 2) * 64 + hb * 4 + (gc & 3);   // gate = gc>>2, j = gc&3
            float w = W[((size_t)oc * CIN + (ic0 + ici)) * 9 + k];
            s_w2[ici][rem] = packf2(w, w);
        }
        __syncthreads();

        // ---- compute ----
        for (int ici = 0; ici < nic; ici++) {
            // 4x4 input patch -> 4 rows x 3 shifted pairs
            float v[4][4];
#pragma unroll
            for (int r = 0; r < 4; r++)
#pragma unroll
                for (int c = 0; c < 4; c++)
                    v[r][c] = s_in[ici][(ty2 + r) * 34 + (tx2 + c)];

            unsigned long long pin[4][3];
#pragma unroll
            for (int r = 0; r < 4; r++)
#pragma unroll
                for (int kx = 0; kx < 3; kx++)
                    pin[r][kx] = packf2(v[r][kx], v[r][kx + 1]);

#pragma unroll
            for (int gc = 0; gc < 16; gc++) {
                unsigned long long wp[9];
#pragma unroll
                for (int k = 0; k < 9; k++) wp[k] = s_w2[ici][gc * 9 + k];
#pragma unroll
                for (int pr = 0; pr < 2; pr++) {
#pragma unroll
                    for (int ky = 0; ky < 3; ky++)
#pragma unroll
                        for (int kx = 0; kx < 3; kx++)
                            FMA2(acc2[gc * 2 + pr], wp[ky * 3 + kx], pin[pr + ky][kx]);
                }
            }
        }
    }

    // ---- LSTM elementwise update: gate order [i, f, o, g] * 64 channels ----
#pragma unroll
    for (int j = 0; j < 4; j++) {
        const int hid = hb * 4 + j;
        const float bi = bias[hid];
        const float bf = bias[64 + hid];
        const float bo = bias[128 + hid];
        const float bg = bias[192 + hid];
#pragma unroll
        for (int pr = 0; pr < 2; pr++) {
            const int gy = tY0 + ty2 + pr;
            const int gx = tX0 + tx2;          // even -> 8B aligned pair
            const size_t idx = (((size_t)b * 64 + hid) << 12) + gy * 64 + gx;

            float i0, i1, f0, f1, o0, o1, q0, q1;
            unpackf2(acc2[(j) * 2 + pr],      i0, i1);
            unpackf2(acc2[(4 + j) * 2 + pr],  f0, f1);
            unpackf2(acc2[(8 + j) * 2 + pr],  o0, o1);
            unpackf2(acc2[(12 + j) * 2 + pr], q0, q1);

            float2 cold = *reinterpret_cast<const float2*>(&C[idx]);
            float cn0 = fsig(f0 + bf) * cold.x + fsig(i0 + bi) * ftanh(q0 + bg);
            float cn1 = fsig(f1 + bf) * cold.y + fsig(i1 + bi) * ftanh(q1 + bg);
            float h0v = fsig(o0 + bo) * ftanh(cn0);
            float h1v = fsig(o1 + bo) * ftanh(cn1);
            *reinterpret_cast<float2*>(&C[idx])    = make_float2(cn0, cn1);
            *reinterpret_cast<float2*>(&Hout[idx]) = make_float2(h0v, h1v);
        }
    }
}

// 1x1 conv head (64 -> 1) + ReLU over h1 final state.
__global__ void head_kernel(const float* __restrict__ h1,
                            const float* __restrict__ wh,
                            const float* __restrict__ bh,
                            float* __restrict__ out)
{
    int idx = blockIdx.x * blockDim.x + threadIdx.x;  // 65536 = 16 * 4096
    int b   = idx >> 12;
    int pix = idx & 4095;
    const float* base = h1 + (((size_t)b * 64) << 12) + pix;
    float s = bh[0];
#pragma unroll
    for (int c = 0; c < 64; c++)
        s = fmaf(wh[c], base[(size_t)c << 12], s);
    out[idx] = fmaxf(s, 0.f);
}

extern "C" void kernel_launch(void* const* d_in, const int* in_sizes, int n_in,
                              void* d_out, int out_size)
{
    const float* x  = (const float*)d_in[0];   // [16,16,1,64,64]
    const float* w0 = (const float*)d_in[1];   // [256,65,3,3]
    const float* b0 = (const float*)d_in[2];   // [256]
    const float* w1 = (const float*)d_in[3];   // [256,128,3,3]
    const float* b1 = (const float*)d_in[4];   // [256]
    const float* wh = (const float*)d_in[5];   // [1,64,1,1]
    const float* bh = (const float*)d_in[6];   // [1]
    float* out = (float*)d_out;                // [16,1,64,64]

    float *h0, *c0, *h1, *c1;
    cudaGetSymbolAddress((void**)&h0, g_h0);
    cudaGetSymbolAddress((void**)&c0, g_c0);
    cudaGetSymbolAddress((void**)&h1, g_h1);
    cudaGetSymbolAddress((void**)&c1, g_c1);

    zero_state_kernel<<<HSZ / 256, 256>>>();

    dim3 grid(4, 16, 16);
    for (int t = 0; t < 16; t++) {
        float* h0r = h0 + (size_t)(t & 1) * HSZ;
        float* h0w = h0 + (size_t)((t + 1) & 1) * HSZ;
        float* h1r = h1 + (size_t)(t & 1) * HSZ;
        float* h1w = h1 + (size_t)((t + 1) & 1) * HSZ;
        // layer 0: input = [x_t (1ch) ; h0_prev (64ch)]
        convlstm_step<1><<<grid, 256>>>(x + (size_t)t * 4096, 16 * 4096,
                                        h0r, w0, b0, c0, h0w);
        // layer 1: input = [h0_new (64ch) ; h1_prev (64ch)]
        convlstm_step<64><<<grid, 256>>>(h0w, 64 * 4096,
                                         h1r, w1, b1, c1, h1w);
    }
    // after t=15, new h1 lives in buffer ((15+1)&1) = 0
    head_kernel<<<65536 / 256, 256>>>(h1, wh, bh, out);
}

// round 10
// speedup vs baseline: 2.6023x; 2.6023x over previous
#include <cuda_runtime.h>
#include <cuda_bf16.h>
#include <cstdint>

// ---------------------------------------------------------------------------
// ConvLSTM via warp-level mma.sync bf16 (split hi/lo for ~fp32 accuracy).
// The harness PTX target is compute_103 (no 'a'), so tcgen05 is unavailable;
// mma.sync.m16n8k16.bf16 is baseline PTX and engages the tensor pipe.
//
// Per (layer,t,b,row): gates[256, 64] = W[256, K=CIN*9] @ im2col[K, 64]
//  - CTA: 256 thr (8 warps), warp tile M=32 x N=64, 64 f32 acc/thread
//  - K chunks of 16, double-buffered SMEM, b32 units permuted [0,4,1,5,2,6,3,7]
//    so each fragment is one LDS.64
//  - operand split: w = hi + lo (bf16 each); D ~= Ah*Bh + Ah*Bl + Al*Bh
//  - LSTM epilogue fused via SMEM transpose (reuses staging SMEM)
// ---------------------------------------------------------------------------

#define HSZ (16 * 64 * 64 * 64)

__device__ float g_h0[2][HSZ];
__device__ float g_c0[HSZ];
__device__ float g_h1[2][HSZ];
__device__ float g_c1[HSZ];

// packed bf16 hi/lo weight k-pairs: [kpair][256 oc]
#define NP0 296   // layer0: ceil(585/16)=37 chunks * 8 pairs
#define NP1 576   // layer1: 1152/16=72 chunks * 8 pairs
__device__ uint32_t g_wh0[NP0 * 256], g_wl0[NP0 * 256];
__device__ uint32_t g_wh1[NP1 * 256], g_wl1[NP1 * 256];

__device__ __forceinline__ float fsig(float x) { return 1.f / (1.f + __expf(-x)); }
__device__ __forceinline__ float ftanh(float x) {
    return 2.f / (1.f + __expf(-2.f * x)) - 1.f;
}

#define MMA16816(Cr, Ar, Br) \
    asm volatile("mma.sync.aligned.m16n8k16.row.col.f32.bf16.bf16.f32 " \
        "{%0,%1,%2,%3}, {%4,%5,%6,%7}, {%8,%9}, {%0,%1,%2,%3};" \
        : "+f"((Cr)[0]), "+f"((Cr)[1]), "+f"((Cr)[2]), "+f"((Cr)[3]) \
        : "r"((Ar)[0]), "r"((Ar)[1]), "r"((Ar)[2]), "r"((Ar)[3]), \
          "r"((Br)[0]), "r"((Br)[1]))

__global__ void zero_state_kernel() {
    int i = blockIdx.x * blockDim.x + threadIdx.x;
    if (i < HSZ) {
        g_h0[0][i] = 0.f;
        g_c0[i]    = 0.f;
        g_h1[0][i] = 0.f;
        g_c1[i]    = 0.f;
    }
}

// Build hi/lo bf16 packed weight pair arrays.
// k order: kt outer, ic inner (k = kt*CIN + ic). Wh/Wl[u][oc] packs k=2u,2u+1.
__global__ void build_wpairs(const float* __restrict__ W,
                             uint32_t* __restrict__ Wh,
                             uint32_t* __restrict__ Wl,
                             int CIN, int npairs) {
    int idx = blockIdx.x * blockDim.x + threadIdx.x;
    if (idx >= npairs * 256) return;
    int oc = idx & 255;
    int u  = idx >> 8;
    int NK = CIN * 9;
    uint32_t h2 = 0, l2 = 0;
#pragma unroll
    for (int e = 0; e < 2; e++) {
        int k = 2 * u + e;
        float v = 0.f;
        if (k < NK) {
            int kt = k / CIN, ic = k - kt * CIN;
            v = W[((size_t)oc * CIN + ic) * 9 + kt];
        }
        __nv_bfloat16 hb = __float2bfloat16(v);
        float hf = __bfloat162float(hb);
        __nv_bfloat16 lb = __float2bfloat16(v - hf);
        h2 |= (uint32_t)__bfloat16_as_ushort(hb) << (16 * e);
        l2 |= (uint32_t)__bfloat16_as_ushort(lb) << (16 * e);
    }
    Wh[(size_t)u * 256 + oc] = h2;
    Wl[(size_t)u * 256 + oc] = l2;
}

// SMEM layout (u32 units), pitch 10 per 8-unit chunk row:
//   AsH: buf0 @0, buf1 @2560   (256 rows x 10)
//   AsL: @5120, @7680
//   BsH: @10240, @10880        (64 rows x 10)
//   BsL: @11520, @12160
// epilogue sep (float[256][65]) unions over the whole thing.
#define DYN_SMEM (256 * 65 * 4)

template <int CHA>
__global__ void __launch_bounds__(256, 2)
convlstm_mma(const float* __restrict__ A, int aBatchStride,
             const float* __restrict__ Hin,
             const uint32_t* __restrict__ Wh,
             const uint32_t* __restrict__ Wl,
             const float* __restrict__ bias,
             float* __restrict__ C,
             float* __restrict__ Hout)
{
    constexpr int CIN = CHA + 64;
    constexpr int NK  = CIN * 9;
    constexpr int NCH = (NK + 15) / 16;
    extern __shared__ uint32_t sm[];
    float* sep = (float*)sm;

    const int tid = threadIdx.x;
    const int wid = tid >> 5;
    const int lid = tid & 31;
    const int g   = lid >> 2;      // fragment group row
    const int t   = lid & 3;       // thread-in-group
    const int b   = blockIdx.y;
    const int y0  = blockIdx.x;    // image row

    const float* Abase = A + (size_t)b * aBatchStride;
    const float* Hbase = Hin + ((size_t)b * 64) * 4096;

    float acc[2][8][4];
#pragma unroll
    for (int i = 0; i < 2; i++)
#pragma unroll
        for (int j = 0; j < 8; j++)
#pragma unroll
            for (int k = 0; k < 4; k++) acc[i][j][k] = 0.f;

    const int bn  = tid & 63;      // pixel x for B staging
    const int bu2 = tid >> 6;      // unit group for B staging

    // ---- main K loop: stage next chunk, compute current, one sync ----
    for (int c = 0; c < NCH + 1; c++) {
        if (c < NCH) {
            const int buf = c & 1;
            // A: thread = oc row, 8 units
            {
                const uint32_t* srcH = Wh + (size_t)(c * 8) * 256 + tid;
                const uint32_t* srcL = Wl + (size_t)(c * 8) * 256 + tid;
                uint32_t* dH = sm + buf * 2560 + tid * 10;
                uint32_t* dL = sm + 5120 + buf * 2560 + tid * 10;
#pragma unroll
                for (int u = 0; u < 8; u++) {
                    int pos = 2 * (u & 3) + (u >> 2);
                    dH[pos] = srcH[u * 256];
                    dL[pos] = srcL[u * 256];
                }
            }
            // B: thread = (pixel bn, unit pair bu2) -> units bu2, bu2+4
            {
                uint32_t* bH = sm + 10240 + buf * 640 + bn * 10;
                uint32_t* bL = sm + 11520 + buf * 640 + bn * 10;
#pragma unroll
                for (int s = 0; s < 2; s++) {
                    const int uu  = bu2 + 4 * s;
                    const int pos = 2 * bu2 + s;
                    uint32_t h2 = 0, l2 = 0;
#pragma unroll
                    for (int e = 0; e < 2; e++) {
                        int k = (c * 8 + uu) * 2 + e;
                        float v = 0.f;
                        if (k < NK) {
                            int kt = k / CIN, ic = k - kt * CIN;
                            int ky = kt / 3, kx = kt - ky * 3;
                            int y = y0 + ky - 1, x = bn + kx - 1;
                            if ((unsigned)y < 64u && (unsigned)x < 64u) {
                                const float* pl = (ic < CHA)
                                    ? (Abase + (size_t)ic * 4096)
                                    : (Hbase + (size_t)(ic - CHA) * 4096);
                                v = __ldg(pl + y * 64 + x);
                            }
                        }
                        __nv_bfloat16 hb = __float2bfloat16(v);
                        float hf = __bfloat162float(hb);
                        __nv_bfloat16 lb = __float2bfloat16(v - hf);
                        h2 |= (uint32_t)__bfloat16_as_ushort(hb) << (16 * e);
                        l2 |= (uint32_t)__bfloat16_as_ushort(lb) << (16 * e);
                    }
                    bH[pos] = h2;
                    bL[pos] = l2;
                }
            }
        }

        if (c > 0) {
            const int buf = (c - 1) & 1;
            const uint32_t* asH = sm + buf * 2560;
            const uint32_t* asL = sm + 5120 + buf * 2560;
            const uint32_t* bsH = sm + 10240 + buf * 640;
            const uint32_t* bsL = sm + 11520 + buf * 640;

            uint32_t aH[2][4], aL[2][4];
#pragma unroll
            for (int ma = 0; ma < 2; ma++) {
                const int row = wid * 32 + 16 * ma + g;
                uint2 p  = *(const uint2*)(asH + row * 10 + 2 * t);
                uint2 q  = *(const uint2*)(asH + (row + 8) * 10 + 2 * t);
                aH[ma][0] = p.x;  aH[ma][1] = q.x;
                aH[ma][2] = p.y;  aH[ma][3] = q.y;
                uint2 pl = *(const uint2*)(asL + row * 10 + 2 * t);
                uint2 ql = *(const uint2*)(asL + (row + 8) * 10 + 2 * t);
                aL[ma][0] = pl.x; aL[ma][1] = ql.x;
                aL[ma][2] = pl.y; aL[ma][3] = ql.y;
            }
#pragma unroll
            for (int h = 0; h < 2; h++) {
                uint32_t bH[4][2], bL[4][2];
#pragma unroll
                for (int na = 0; na < 4; na++) {
                    const int col = 8 * (4 * h + na) + g;
                    uint2 pb = *(const uint2*)(bsH + col * 10 + 2 * t);
                    bH[na][0] = pb.x; bH[na][1] = pb.y;
                    uint2 qb = *(const uint2*)(bsL + col * 10 + 2 * t);
                    bL[na][0] = qb.x; bL[na][1] = qb.y;
                }
#pragma unroll
                for (int ma = 0; ma < 2; ma++)
#pragma unroll
                    for (int na = 0; na < 4; na++) {
                        MMA16816(acc[ma][4 * h + na], aH[ma], bH[na]);
                        MMA16816(acc[ma][4 * h + na], aH[ma], bL[na]);
                        MMA16816(acc[ma][4 * h + na], aL[ma], bH[na]);
                    }
            }
        }
        __syncthreads();
    }

    // ---- epilogue: transpose gates to SMEM, fused LSTM update ----
#pragma unroll
    for (int ma = 0; ma < 2; ma++)
#pragma unroll
        for (int na = 0; na < 8; na++) {
            const int row = wid * 32 + 16 * ma + g;
            const int col = 8 * na + 2 * t;
            sep[row * 65 + col]           = acc[ma][na][0];
            sep[row * 65 + col + 1]       = acc[ma][na][1];
            sep[(row + 8) * 65 + col]     = acc[ma][na][2];
            sep[(row + 8) * 65 + col + 1] = acc[ma][na][3];
        }
    __syncthreads();

#pragma unroll
    for (int j = 0; j < 16; j++) {
        const int item = tid + 256 * j;       // 0..4095
        const int hid  = item >> 6;
        const int x    = item & 63;
        const float iv = sep[hid * 65 + x]         + bias[hid];
        const float fv = sep[(64 + hid) * 65 + x]  + bias[64 + hid];
        const float ov = sep[(128 + hid) * 65 + x] + bias[128 + hid];
        const float gv = sep[(192 + hid) * 65 + x] + bias[192 + hid];
        const size_t idx = (((size_t)b * 64 + hid) << 12) + y0 * 64 + x;
        const float cn = fsig(fv) * C[idx] + fsig(iv) * ftanh(gv);
        C[idx]    = cn;
        Hout[idx] = fsig(ov) * ftanh(cn);
    }
}

// 1x1 conv head (64 -> 1) + ReLU over final h1.
__global__ void head_kernel(const float* __restrict__ h1,
                            const float* __restrict__ wh,
                            const float* __restrict__ bh,
                            float* __restrict__ out)
{
    int idx = blockIdx.x * blockDim.x + threadIdx.x;
    int b   = idx >> 12;
    int pix = idx & 4095;
    const float* base = h1 + (((size_t)b * 64) << 12) + pix;
    float s = bh[0];
#pragma unroll
    for (int c = 0; c < 64; c++)
        s = fmaf(wh[c], base[(size_t)c << 12], s);
    out[idx] = fmaxf(s, 0.f);
}

// ------------------------------- launch -------------------------------------

extern "C" void kernel_launch(void* const* d_in, const int* in_sizes, int n_in,
                              void* d_out, int out_size)
{
    const float* x  = (const float*)d_in[0];   // [16,16,1,64,64]
    const float* w0 = (const float*)d_in[1];   // [256,65,3,3]
    const float* b0 = (const float*)d_in[2];   // [256]
    const float* w1 = (const float*)d_in[3];   // [256,128,3,3]
    const float* b1 = (const float*)d_in[4];   // [256]
    const float* wh = (const float*)d_in[5];   // [1,64,1,1]
    const float* bh = (const float*)d_in[6];   // [1]
    float* out = (float*)d_out;                // [16,1,64,64]

    float *h0, *c0, *h1, *c1;
    uint32_t *wh0, *wl0, *wh1, *wl1;
    cudaGetSymbolAddress((void**)&h0,  g_h0);
    cudaGetSymbolAddress((void**)&c0,  g_c0);
    cudaGetSymbolAddress((void**)&h1,  g_h1);
    cudaGetSymbolAddress((void**)&c1,  g_c1);
    cudaGetSymbolAddress((void**)&wh0, g_wh0);
    cudaGetSymbolAddress((void**)&wl0, g_wl0);
    cudaGetSymbolAddress((void**)&wh1, g_wh1);
    cudaGetSymbolAddress((void**)&wl1, g_wl1);

    cudaFuncSetAttribute(convlstm_mma<1>,
                         cudaFuncAttributeMaxDynamicSharedMemorySize, DYN_SMEM);
    cudaFuncSetAttribute(convlstm_mma<64>,
                         cudaFuncAttributeMaxDynamicSharedMemorySize, DYN_SMEM);

    zero_state_kernel<<<HSZ / 256, 256>>>();
    build_wpairs<<<NP0, 256>>>(w0, wh0, wl0, 65, NP0);
    build_wpairs<<<NP1, 256>>>(w1, wh1, wl1, 128, NP1);

    dim3 grid(64, 16);   // (image row, batch)
    for (int t = 0; t < 16; t++) {
        float* h0r = h0 + (size_t)(t & 1) * HSZ;
        float* h0w = h0 + (size_t)((t + 1) & 1) * HSZ;
        float* h1r = h1 + (size_t)(t & 1) * HSZ;
        float* h1w = h1 + (size_t)((t + 1) & 1) * HSZ;
        // layer 0: input = [x_t (1ch) ; h0_prev (64ch)]
        convlstm_mma<1><<<grid, 256, DYN_SMEM>>>(
            x + (size_t)t * 4096, 16 * 4096, h0r, wh0, wl0, b0, c0, h0w);
        // layer 1: input = [h0_new (64ch) ; h1_prev (64ch)]
        convlstm_mma<64><<<grid, 256, DYN_SMEM>>>(
            h0w, 64 * 4096, h1r, wh1, wl1, b1, c1, h1w);
    }
    head_kernel<<<65536 / 256, 256>>>(h1, wh, bh, out);   // final h1 in buf 0
}

// round 11
// speedup vs baseline: 3.3186x; 1.2753x over previous
#include <cuda_runtime.h>
#include <cuda_bf16.h>
#include <cstdint>

// ---------------------------------------------------------------------------
// ConvLSTM via mma.sync bf16 (hi/lo split, 3 MMAs ~ fp32 accuracy), sm_103a.
// R11: ALU-bound fix — hidden/input states stored as PRE-SPLIT packed bf16x2
// channel-pair planes (u32 per (2ch, px), hi & lo). B-staging = one coalesced
// predicated LDG.32 per (pair,px); all fp32->bf16 splitting happens once, in
// the epilogue of the producing step (or at setup for x).
//
// K-order (pairs): layer0: per tap 33 pairs = 32 h-pairs + (x,0) pair (CIN 65
// repacked); layer1: per tap 64 pairs = 32 h0_new-pairs + 32 h1_prev-pairs.
// Weight pair arrays are built to match. Chunks of 16 K (8 pairs), double-
// buffered SMEM, b32 k-permutation [0,4,1,5,2,6,3,7] -> LDS.64 fragments.
// ---------------------------------------------------------------------------

#define HSZ   (16 * 64 * 64 * 64)     // planar float state [b][64ch][4096]
#define PLSZ  (16 * 32 * 4096)        // pair planes [b][32 pairs][4096] (u32)

__device__ float    g_c0[HSZ], g_c1[HSZ];
__device__ uint32_t g_h0h[2][PLSZ], g_h0l[2][PLSZ];
__device__ uint32_t g_h1h[2][PLSZ], g_h1l[2][PLSZ];
__device__ uint32_t g_xph[16 * 16 * 4096], g_xpl[16 * 16 * 4096]; // [t][b][px]

// packed bf16 hi/lo weight k-pairs, K-order above: [pair][256 ocp]
#define NP0 304   // layer0: 38 chunks * 8 (9*33=297 real, rest zero)
#define NP1 576   // layer1: 72 chunks * 8
__device__ uint32_t g_wh0[NP0 * 256], g_wl0[NP0 * 256];
__device__ uint32_t g_wh1[NP1 * 256], g_wl1[NP1 * 256];

__device__ __forceinline__ float fsig(float x) { return 1.f / (1.f + __expf(-x)); }
__device__ __forceinline__ float ftanh(float x) {
    return 2.f / (1.f + __expf(-2.f * x)) - 1.f;
}

// pack (v0,v1) as bf16x2 hi word; residuals as bf16x2 lo word
__device__ __forceinline__ uint32_t pack_hl(float v0, float v1, uint32_t& lo) {
    __nv_bfloat16 h0 = __float2bfloat16(v0);
    __nv_bfloat16 h1 = __float2bfloat16(v1);
    float r0 = v0 - __bfloat162float(h0);
    float r1 = v1 - __bfloat162float(h1);
    lo = (uint32_t)__bfloat16_as_ushort(__float2bfloat16(r0))
       | ((uint32_t)__bfloat16_as_ushort(__float2bfloat16(r1)) << 16);
    return (uint32_t)__bfloat16_as_ushort(h0)
         | ((uint32_t)__bfloat16_as_ushort(h1) << 16);
}
__device__ __forceinline__ float bflo(uint32_t u) {
    return __bfloat162float(__ushort_as_bfloat16((unsigned short)(u & 0xffff)));
}
__device__ __forceinline__ float bfhi(uint32_t u) {
    return __bfloat162float(__ushort_as_bfloat16((unsigned short)(u >> 16)));
}

#define MMA16816(Cr, Ar, Br) \
    asm volatile("mma.sync.aligned.m16n8k16.row.col.f32.bf16.bf16.f32 " \
        "{%0,%1,%2,%3}, {%4,%5,%6,%7}, {%8,%9}, {%0,%1,%2,%3};" \
        : "+f"((Cr)[0]), "+f"((Cr)[1]), "+f"((Cr)[2]), "+f"((Cr)[3]) \
        : "r"((Ar)[0]), "r"((Ar)[1]), "r"((Ar)[2]), "r"((Ar)[3]), \
          "r"((Br)[0]), "r"((Br)[1]))

// ------------------------------ prep kernels --------------------------------

__global__ void zero_state_kernel() {
    int i = blockIdx.x * blockDim.x + threadIdx.x;
    if (i < HSZ) { g_c0[i] = 0.f; g_c1[i] = 0.f; }
    if (i < PLSZ) {
        g_h0h[0][i] = 0u; g_h0l[0][i] = 0u;
        g_h1h[0][i] = 0u; g_h1l[0][i] = 0u;
    }
}

// x pair planes: [t][b][px] <- x[b][t][0][px], pair = (x, 0)
__global__ void build_xpairs(const float* __restrict__ x) {
    int idx = blockIdx.x * blockDim.x + threadIdx.x;   // 16*16*4096
    int t  = idx >> 16;
    int b  = (idx >> 12) & 15;
    int px = idx & 4095;
    float v = x[(((size_t)b * 16 + t) << 12) + px];
    uint32_t lo;
    uint32_t hi = pack_hl(v, 0.f, lo);
    g_xph[idx] = hi;
    g_xpl[idx] = lo;
}

// layer0 weights: pair u: kt=u/33, j=u%33; j<32 -> ic (1+2j, 2+2j); j==32 -> (0, -)
__global__ void build_w0() {
    int idx = blockIdx.x * blockDim.x + threadIdx.x;   // NP0*256
    if (idx >= NP0 * 256) return;
    int oc = idx & 255, u = idx >> 8;
    float v0 = 0.f, v1 = 0.f;
    if (u < 297) {
        int kt = u / 33, j = u - kt * 33;
        const float* W = (const float*)0;  // patched via param-less trick? no:
        (void)W;
    }
    // real body below (kept single definition with args)
}

// (single-arg versions used instead)
__global__ void build_w0k(const float* __restrict__ W) {
    int idx = blockIdx.x * blockDim.x + threadIdx.x;
    if (idx >= NP0 * 256) return;
    int oc = idx & 255, u = idx >> 8;
    float v0 = 0.f, v1 = 0.f;
    if (u < 297) {
        int kt = u / 33, j = u - kt * 33;
        if (j < 32) {
            v0 = W[((size_t)oc * 65 + (1 + 2 * j)) * 9 + kt];
            v1 = W[((size_t)oc * 65 + (2 + 2 * j)) * 9 + kt];
        } else {
            v0 = W[((size_t)oc * 65 + 0) * 9 + kt];
        }
    }
    uint32_t lo;
    uint32_t hi = pack_hl(v0, v1, lo);
    g_wh0[idx] = hi;
    g_wl0[idx] = lo;
}

__global__ void build_w1k(const float* __restrict__ W) {
    int idx = blockIdx.x * blockDim.x + threadIdx.x;
    if (idx >= NP1 * 256) return;
    int oc = idx & 255, u = idx >> 8;
    int kt = u >> 6, j = u & 63;
    float v0 = W[((size_t)oc * 128 + 2 * j) * 9 + kt];
    float v1 = W[((size_t)oc * 128 + 2 * j + 1) * 9 + kt];
    uint32_t lo;
    uint32_t hi = pack_hl(v0, v1, lo);
    g_wh1[idx] = hi;
    g_wl1[idx] = lo;
}

// ------------------------------ main kernel ---------------------------------
// SMEM (u32 units, pitch 10 per 8-unit chunk row):
//   AsH buf0 @0, buf1 @2560; AsL @5120,@7680 (256 rows)
//   BsH @10240,@10880; BsL @11520,@12160    (64 rows)
// epilogue: float sep[256][65] unions over everything.
#define DYN_SMEM (256 * 65 * 4)

template <int LAYER>
__global__ void __launch_bounds__(256, 2)
convlstm_mma(const uint32_t* __restrict__ Wh, const uint32_t* __restrict__ Wl,
             const uint32_t* __restrict__ pAh, const uint32_t* __restrict__ pAl,
             const uint32_t* __restrict__ pBh, const uint32_t* __restrict__ pBl,
             const float* __restrict__ bias,
             float* __restrict__ C,
             uint32_t* __restrict__ oH, uint32_t* __restrict__ oL)
{
    constexpr int PPT = (LAYER == 0) ? 33 : 64;   // pairs per tap
    constexpr int NCH = (LAYER == 0) ? 38 : 72;   // 16-K chunks
    extern __shared__ uint32_t sm[];
    float* sep = (float*)sm;

    const int tid = threadIdx.x;
    const int wid = tid >> 5;
    const int lid = tid & 31;
    const int g   = lid >> 2;
    const int t   = lid & 3;
    const int b   = blockIdx.y;
    const int y0  = blockIdx.x;

    float acc[2][8][4];
#pragma unroll
    for (int i = 0; i < 2; i++)
#pragma unroll
        for (int j = 0; j < 8; j++)
#pragma unroll
            for (int k = 0; k < 4; k++) acc[i][j][k] = 0.f;

    const int bn  = tid & 63;
    const int bu2 = tid >> 6;

    for (int c = 0; c < NCH + 1; c++) {
        if (c < NCH) {
            const int buf = c & 1;
            // ---- A: thread = ocp row, 8 pairs hi+lo ----
            {
                const uint32_t* srcH = Wh + (size_t)(c * 8) * 256 + tid;
                const uint32_t* srcL = Wl + (size_t)(c * 8) * 256 + tid;
                uint32_t* dH = sm + buf * 2560 + tid * 10;
                uint32_t* dL = sm + 5120 + buf * 2560 + tid * 10;
#pragma unroll
                for (int u = 0; u < 8; u++) {
                    int pos = 2 * (u & 3) + (u >> 2);
                    dH[pos] = srcH[u * 256];
                    dL[pos] = srcL[u * 256];
                }
            }
            // ---- B: thread = (px, pair grp); one LDG.32 per (pair,hi/lo) ----
            {
                uint32_t* bH = sm + 10240 + buf * 640 + bn * 10;
                uint32_t* bL = sm + 11520 + buf * 640 + bn * 10;
#pragma unroll
                for (int s = 0; s < 2; s++) {
                    const int uu = bu2 + 4 * s;
                    const int u  = c * 8 + uu;
                    const int kt = u / PPT;            // warp-uniform
                    const int j  = u - kt * PPT;
                    const int ky = kt / 3;
                    const int kx = kt - ky * 3;
                    const int y  = y0 + ky - 1;
                    const int x  = bn + kx - 1;
                    const bool ok = ((unsigned)y < 64u) && ((unsigned)x < 64u);
                    const int poff = y * 64 + x;
                    const uint32_t* sH;
                    const uint32_t* sL;
                    if (LAYER == 0) {
                        if (j < 32) {
                            sH = pAh + ((size_t)(b * 32 + j) << 12);
                            sL = pAl + ((size_t)(b * 32 + j) << 12);
                        } else {
                            sH = pBh + ((size_t)b << 12);   // x pair plane
                            sL = pBl + ((size_t)b << 12);
                        }
                    } else {
                        if (j < 32) {
                            sH = pAh + ((size_t)(b * 32 + j) << 12);
                            sL = pAl + ((size_t)(b * 32 + j) << 12);
                        } else {
                            sH = pBh + ((size_t)(b * 32 + j - 32) << 12);
                            sL = pBl + ((size_t)(b * 32 + j - 32) << 12);
                        }
                    }
                    uint32_t vh = 0u, vl = 0u;
                    if (ok) { vh = __ldg(sH + poff); vl = __ldg(sL + poff); }
                    const int pos = 2 * bu2 + s;
                    bH[pos] = vh;
                    bL[pos] = vl;
                }
            }
        }

        if (c > 0) {
            const int buf = (c - 1) & 1;
            const uint32_t* asH = sm + buf * 2560;
            const uint32_t* asL = sm + 5120 + buf * 2560;
            const uint32_t* bsH = sm + 10240 + buf * 640;
            const uint32_t* bsL = sm + 11520 + buf * 640;

            uint32_t aH[2][4], aL[2][4];
#pragma unroll
            for (int ma = 0; ma < 2; ma++) {
                const int row = wid * 32 + 16 * ma + g;
                uint2 p  = *(const uint2*)(asH + row * 10 + 2 * t);
                uint2 q  = *(const uint2*)(asH + (row + 8) * 10 + 2 * t);
                aH[ma][0] = p.x;  aH[ma][1] = q.x;
                aH[ma][2] = p.y;  aH[ma][3] = q.y;
                uint2 pl = *(const uint2*)(asL + row * 10 + 2 * t);
                uint2 ql = *(const uint2*)(asL + (row + 8) * 10 + 2 * t);
                aL[ma][0] = pl.x; aL[ma][1] = ql.x;
                aL[ma][2] = pl.y; aL[ma][3] = ql.y;
            }
#pragma unroll
            for (int h = 0; h < 2; h++) {
                uint32_t bH[4][2], bL[4][2];
#pragma unroll
                for (int na = 0; na < 4; na++) {
                    const int col = 8 * (4 * h + na) + g;
                    uint2 pb = *(const uint2*)(bsH + col * 10 + 2 * t);
                    bH[na][0] = pb.x; bH[na][1] = pb.y;
                    uint2 qb = *(const uint2*)(bsL + col * 10 + 2 * t);
                    bL[na][0] = qb.x; bL[na][1] = qb.y;
                }
#pragma unroll
                for (int ma = 0; ma < 2; ma++)
#pragma unroll
                    for (int na = 0; na < 4; na++) {
                        MMA16816(acc[ma][4 * h + na], aH[ma], bH[na]);
                        MMA16816(acc[ma][4 * h + na], aH[ma], bL[na]);
                        MMA16816(acc[ma][4 * h + na], aL[ma], bH[na]);
                    }
            }
        }
        __syncthreads();
    }

    // ---- epilogue: transpose to SMEM, fused LSTM, write split pair planes ----
#pragma unroll
    for (int ma = 0; ma < 2; ma++)
#pragma unroll
        for (int na = 0; na < 8; na++) {
            const int row = wid * 32 + 16 * ma + g;
            const int col = 8 * na + 2 * t;
            sep[row * 65 + col]           = acc[ma][na][0];
            sep[row * 65 + col + 1]       = acc[ma][na][1];
            sep[(row + 8) * 65 + col]     = acc[ma][na][2];
            sep[(row + 8) * 65 + col + 1] = acc[ma][na][3];
        }
    __syncthreads();

#pragma unroll
    for (int j = 0; j < 8; j++) {
        const int item = tid + 256 * j;        // 0..2047 = (ph 0..31, x 0..63)
        const int ph = item >> 6;
        const int x  = item & 63;
        float hv[2];
#pragma unroll
        for (int e = 0; e < 2; e++) {
            const int hid = 2 * ph + e;
            const float iv = sep[hid * 65 + x]         + bias[hid];
            const float fv = sep[(64 + hid) * 65 + x]  + bias[64 + hid];
            const float ov = sep[(128 + hid) * 65 + x] + bias[128 + hid];
            const float gv = sep[(192 + hid) * 65 + x] + bias[192 + hid];
            const size_t idx = (((size_t)b * 64 + hid) << 12) + y0 * 64 + x;
            const float cn = fsig(fv) * C[idx] + fsig(iv) * ftanh(gv);
            C[idx] = cn;
            hv[e] = fsig(ov) * ftanh(cn);
        }
        uint32_t lo;
        uint32_t hi = pack_hl(hv[0], hv[1], lo);
        const size_t op = ((size_t)(b * 32 + ph) << 12) + y0 * 64 + x;
        oH[op] = hi;
        oL[op] = lo;
    }
}

// 1x1 conv head (64 -> 1) + ReLU; reconstructs h1 = hi + lo from pair planes.
__global__ void head_kernel(const uint32_t* __restrict__ h1h,
                            const uint32_t* __restrict__ h1l,
                            const float* __restrict__ wh,
                            const float* __restrict__ bh,
                            float* __restrict__ out)
{
    int idx = blockIdx.x * blockDim.x + threadIdx.x;   // 65536
    int b   = idx >> 12;
    int pix = idx & 4095;
    float s = bh[0];
#pragma unroll
    for (int ph = 0; ph < 32; ph++) {
        const size_t op = ((size_t)(b * 32 + ph) << 12) + pix;
        uint32_t h = h1h[op], l = h1l[op];
        float v0 = bflo(h) + bflo(l);
        float v1 = bfhi(h) + bfhi(l);
        s = fmaf(wh[2 * ph], v0, s);
        s = fmaf(wh[2 * ph + 1], v1, s);
    }
    out[idx] = fmaxf(s, 0.f);
}

// ------------------------------- launch -------------------------------------

extern "C" void kernel_launch(void* const* d_in, const int* in_sizes, int n_in,
                              void* d_out, int out_size)
{
    const float* x  = (const float*)d_in[0];
    const float* w0 = (const float*)d_in[1];
    const float* b0 = (const float*)d_in[2];
    const float* w1 = (const float*)d_in[3];
    const float* b1 = (const float*)d_in[4];
    const float* wh = (const float*)d_in[5];
    const float* bh = (const float*)d_in[6];
    float* out = (float*)d_out;

    float *c0, *c1;
    uint32_t *h0h, *h0l, *h1h, *h1l, *xph, *xpl, *wh0, *wl0, *wh1, *wl1;
    cudaGetSymbolAddress((void**)&c0,  g_c0);
    cudaGetSymbolAddress((void**)&c1,  g_c1);
    cudaGetSymbolAddress((void**)&h0h, g_h0h);
    cudaGetSymbolAddress((void**)&h0l, g_h0l);
    cudaGetSymbolAddress((void**)&h1h, g_h1h);
    cudaGetSymbolAddress((void**)&h1l, g_h1l);
    cudaGetSymbolAddress((void**)&xph, g_xph);
    cudaGetSymbolAddress((void**)&xpl, g_xpl);
    cudaGetSymbolAddress((void**)&wh0, g_wh0);
    cudaGetSymbolAddress((void**)&wl0, g_wl0);
    cudaGetSymbolAddress((void**)&wh1, g_wh1);
    cudaGetSymbolAddress((void**)&wl1, g_wl1);

    cudaFuncSetAttribute(convlstm_mma<0>,
                         cudaFuncAttributeMaxDynamicSharedMemorySize, DYN_SMEM);
    cudaFuncSetAttribute(convlstm_mma<1>,
                         cudaFuncAttributeMaxDynamicSharedMemorySize, DYN_SMEM);

    zero_state_kernel<<<HSZ / 256, 256>>>();
    build_xpairs<<<16 * 16 * 4096 / 256, 256>>>(x);
    build_w0k<<<(NP0 * 256 + 255) / 256, 256>>>(w0);
    build_w1k<<<(NP1 * 256 + 255) / 256, 256>>>(w1);

    dim3 grid(64, 16);
    for (int t = 0; t < 16; t++) {
        const int pr = t & 1, pw = (t + 1) & 1;
        // layer 0: B pairs = [h0_prev pairs ; x pair]
        convlstm_mma<0><<<grid, 256, DYN_SMEM>>>(
            wh0, wl0,
            h0h + (size_t)pr * PLSZ, h0l + (size_t)pr * PLSZ,
            xph + (size_t)t * 16 * 4096, xpl + (size_t)t * 16 * 4096,
            b0, c0,
            h0h + (size_t)pw * PLSZ, h0l + (size_t)pw * PLSZ);
        // layer 1: B pairs = [h0_new pairs ; h1_prev pairs]
        convlstm_mma<1><<<grid, 256, DYN_SMEM>>>(
            wh1, wl1,
            h0h + (size_t)pw * PLSZ, h0l + (size_t)pw * PLSZ,
            h1h + (size_t)pr * PLSZ, h1l + (size_t)pr * PLSZ,
            b1, c1,
            h1h + (size_t)pw * PLSZ, h1l + (size_t)pw * PLSZ);
    }
    // final h1 in ping-pong slot 0
    head_kernel<<<65536 / 256, 256>>>(h1h, h1l, wh, bh, out);
}